// round 8
// baseline (speedup 1.0000x reference)
#include <cuda_runtime.h>
#include <cuda_fp16.h>
#include <cstdint>

// ---------------------------------------------------------------------------
// out[b,h,w,s,co] = ELU( conv3x3_SAME(x, W_s) ),  W_s = mu + n_s*exp(logstd)
// GEMM: C[65536,1024] = A_im2col[65536,576] * W[576,1024]; C row-major == out.
// fp16 m16n8k16 HMMA + LDSM. Warp tile 64x64 (4 warps/CTA): 1.0 smem
// wavefront per HMMA (was 1.5) -> tensor pipe becomes the binding resource.
// ---------------------------------------------------------------------------
#define NS    8
#define CINV  64
#define COUTV 128
#define NTOTV 1024
#define NTAP  9
#define PSTR  72
#define BSTR  72
#define PATCH_HALFS (264 * PSTR)            // 4 h-rows x 66 w
#define BSTAGE_HALFS (128 * BSTR)
#define NSTAGE 4
#define SMEM_TOTAL ((PATCH_HALFS + NSTAGE * BSTAGE_HALFS) * 2)   // 111744 B -> 2 CTA/SM

__device__ __half g_Xh[16 * 64 * 64 * CINV];
__device__ __half g_Wh[NTAP * NTOTV * CINV];

// ============================ helpers ======================================
__device__ __forceinline__ void cp_async16(uint32_t dst, const void* src) {
    asm volatile("cp.async.cg.shared.global [%0], [%1], 16;" :: "r"(dst), "l"(src));
}
__device__ __forceinline__ void cp_commit() { asm volatile("cp.async.commit_group;"); }
template <int N> __device__ __forceinline__ void cp_wait() {
    asm volatile("cp.async.wait_group %0;" :: "n"(N));
}
__device__ __forceinline__ uint32_t smem_u32(const void* p) {
    uint32_t a;
    asm("{ .reg .u64 t; cvta.to.shared.u64 t, %1; cvt.u32.u64 %0, t; }" : "=r"(a) : "l"(p));
    return a;
}
__device__ __forceinline__ void ldsm4(uint32_t& r0, uint32_t& r1, uint32_t& r2,
                                      uint32_t& r3, uint32_t addr) {
    asm volatile("ldmatrix.sync.aligned.m8n8.x4.shared.b16 {%0,%1,%2,%3}, [%4];"
                 : "=r"(r0), "=r"(r1), "=r"(r2), "=r"(r3) : "r"(addr));
}
__device__ __forceinline__ void mma_f16(float* c, const uint32_t* a, const uint32_t* b) {
    asm volatile(
        "mma.sync.aligned.m16n8k16.row.col.f32.f16.f16.f32 "
        "{%0,%1,%2,%3}, {%4,%5,%6,%7}, {%8,%9}, {%0,%1,%2,%3};"
        : "+f"(c[0]), "+f"(c[1]), "+f"(c[2]), "+f"(c[3])
        : "r"(a[0]), "r"(a[1]), "r"(a[2]), "r"(a[3]), "r"(b[0]), "r"(b[1]));
}
__device__ __forceinline__ float elu1(float v) { return v > 0.f ? v : expm1f(v); }

struct Frags { uint32_t a[4][4]; uint32_t b[8][2]; };

// ============================ fused prep kernel ============================
__global__ void prep(const float* __restrict__ x,
                     const float* __restrict__ mu,
                     const float* __restrict__ logstd,
                     const float* __restrict__ noise) {
    int idx = blockIdx.x * blockDim.x + threadIdx.x;      // 1048576 threads
    float4 v = reinterpret_cast<const float4*>(x)[idx];
    __half2* xo = reinterpret_cast<__half2*>(g_Xh) + idx * 2;
    xo[0] = __floats2half2_rn(v.x, v.y);
    xo[1] = __floats2half2_rn(v.z, v.w);
    if (idx < NS * NTAP * CINV * COUTV) {                 // 589824
        int co  = idx & 127;
        int ci  = (idx >> 7) & 63;
        int tap = (idx >> 13) % NTAP;
        int s   = idx / (NTAP << 13);
        int mi  = (tap * CINV + ci) * COUTV + co;
        float w = mu[mi] + noise[idx] * expf(logstd[mi]);
        g_Wh[(tap * NTOTV + s * COUTV + co) * CINV + ci] = __float2half_rn(w);
    }
}

// ============================ conv kernel ==================================
__device__ __forceinline__ void load_B(uint32_t b_u32, int tap, int ntile, int tid) {
    const __half* wb = g_Wh + (size_t)(tap * NTOTV + (ntile << 7)) * CINV;
    #pragma unroll
    for (int i = 0; i < 8; i++) {            // 1024 chunks / 128 threads
        int lin = tid + (i << 7);
        int n = lin >> 3, c = lin & 7;
        cp_async16(b_u32 + (uint32_t)(n * BSTR + (c << 3)) * 2u, wb + n * CINV + (c << 3));
    }
    cp_commit();
}

__device__ __forceinline__ void load_frags(Frags& F, int tap, int kk,
                                           uint32_t pA0, uint32_t bu0, uint32_t b_warp) {
    const int dy = tap / 3 - 1, dx = tap % 3 - 1;
    const uint32_t aBase = pA0 + (uint32_t)((dy * 66 + dx) * PSTR * 2) + (uint32_t)(kk * 32);
    const uint32_t bBase = bu0 + (uint32_t)((tap & 3) * (BSTAGE_HALFS * 2)) + b_warp
                         + (uint32_t)(kk * 32);
    #pragma unroll
    for (int mf = 0; mf < 4; mf++)
        ldsm4(F.a[mf][0], F.a[mf][1], F.a[mf][2], F.a[mf][3],
              aBase + (uint32_t)(mf * 16 * PSTR * 2));
    #pragma unroll
    for (int np = 0; np < 4; np++)
        ldsm4(F.b[2 * np][0], F.b[2 * np][1], F.b[2 * np + 1][0], F.b[2 * np + 1][1],
              bBase + (uint32_t)(np * 16 * BSTR * 2));
}

__global__ __launch_bounds__(128, 2)
void conv_mma_kernel(float* __restrict__ out) {
    extern __shared__ __half smem[];
    const uint32_t patch_u32 = smem_u32(smem);
    const uint32_t bu0 = patch_u32 + PATCH_HALFS * 2u;

    const int tid = threadIdx.x, wid = tid >> 5, lid = tid & 31;
    const int mtile = blockIdx.x, ntile = blockIdx.y;
    const int b  = mtile >> 5;
    const int h0 = (mtile & 31) << 1;
    const int wm = wid & 1, wn = wid >> 1;     // 2x2 warps, tile 64m x 64n

    const uint32_t a_lane = (uint32_t)((lid & 15) * PSTR + (lid >> 4) * 8) * 2u;
    const uint32_t b_lane = (uint32_t)((((lid & 7) + ((lid >> 4) << 3)) * BSTR)
                                       + (((lid >> 3) & 1) << 3)) * 2u;
    const uint32_t pA0    = patch_u32 + (uint32_t)(((wm + 1) * 66 + 1) * PSTR * 2) + a_lane;
    const uint32_t b_warp = (uint32_t)((wn << 6) * BSTR) * 2u + b_lane;

    // ---- prologue: G0 = patch + B(tap0), G1 = B1, G2 = B2 ----
    #pragma unroll
    for (int i = 0; i < 17; i++) {             // 2112 chunks / 128 threads
        int lin = tid + (i << 7);
        if (lin >= 2112) break;
        int row = lin >> 3, c = lin & 7;
        int hh = row / 66, ww = row % 66;
        int h = h0 - 1 + hh, w = ww - 1;
        uint32_t dst = patch_u32 + (uint32_t)(row * PSTR + (c << 3)) * 2u;
        if ((unsigned)h < 64u && (unsigned)w < 64u) {
            cp_async16(dst, g_Xh + (size_t)(((b << 6) + h) * 64 + w) * CINV + (c << 3));
        } else {
            asm volatile("st.shared.v4.b32 [%0], {%1,%1,%1,%1};" :: "r"(dst), "r"(0u) : "memory");
        }
    }
    load_B(bu0, 0, ntile, tid);
    load_B(bu0 + BSTAGE_HALFS * 2u, 1, ntile, tid);
    load_B(bu0 + 2u * BSTAGE_HALFS * 2u, 2, ntile, tid);

    float acc[4][8][4];
    #pragma unroll
    for (int i = 0; i < 4; i++)
        #pragma unroll
        for (int j = 0; j < 8; j++)
            #pragma unroll
            for (int k = 0; k < 4; k++) acc[i][j][k] = 0.f;

    cp_wait<1>();
    __syncthreads();

    Frags f[2];
    load_frags(f[0], 0, 0, pA0, bu0, b_warp);

    #pragma unroll 1
    for (int tap = 0; tap < NTAP; tap++) {
        if (tap >= 1) {
            if (tap < 6) cp_wait<1>(); else cp_wait<0>();
            __syncthreads();
        }
        if (tap + 3 <= 8)
            load_B(bu0 + (uint32_t)(((tap + 3) & 3) * (BSTAGE_HALFS * 2)), tap + 3, ntile, tid);

        #pragma unroll
        for (int kk = 0; kk < 4; kk++) {
            Frags& c = f[kk & 1];
            Frags& n = f[(kk & 1) ^ 1];
            if (kk < 3)          load_frags(n, tap, kk + 1, pA0, bu0, b_warp);
            else if (tap < 8)    load_frags(n, tap + 1, 0, pA0, bu0, b_warp);
            #pragma unroll
            for (int mf = 0; mf < 4; mf++)
                #pragma unroll
                for (int nf = 0; nf < 8; nf++)
                    mma_f16(acc[mf][nf], c.a[mf], c.b[nf]);
        }
    }

    // ---- epilogue: ELU + float2 stores ----
    const int l4 = lid >> 2, lm = lid & 3;
    const int colb = (ntile << 7) + (wn << 6) + lm * 2;
    #pragma unroll
    for (int mf = 0; mf < 4; mf++) {
        int row = (mtile << 7) + wm * 64 + mf * 16 + l4;
        float* o0 = out + (size_t)row * NTOTV + colb;
        float* o1 = o0 + 8 * NTOTV;
        #pragma unroll
        for (int nf = 0; nf < 8; nf++) {
            float2 v0, v1;
            v0.x = elu1(acc[mf][nf][0]); v0.y = elu1(acc[mf][nf][1]);
            v1.x = elu1(acc[mf][nf][2]); v1.y = elu1(acc[mf][nf][3]);
            *reinterpret_cast<float2*>(o0 + nf * 8) = v0;
            *reinterpret_cast<float2*>(o1 + nf * 8) = v1;
        }
    }
}

// ---------------------------------------------------------------------------
extern "C" void kernel_launch(void* const* d_in, const int* in_sizes, int n_in,
                              void* d_out, int out_size) {
    const float* x      = (const float*)d_in[0];
    const float* mu     = (const float*)d_in[1];
    const float* logstd = (const float*)d_in[2];
    const float* noise  = (const float*)d_in[3];
    float* out = (float*)d_out;

    prep<<<4096, 256>>>(x, mu, logstd, noise);

    cudaFuncSetAttribute(conv_mma_kernel,
                         cudaFuncAttributeMaxDynamicSharedMemorySize, SMEM_TOTAL);
    dim3 grid(512, 8);
    conv_mma_kernel<<<grid, 128, SMEM_TOTAL>>>(out);
}

// round 9
// speedup vs baseline: 1.0756x; 1.0756x over previous
#include <cuda_runtime.h>
#include <cuda_fp16.h>
#include <cstdint>

// ---------------------------------------------------------------------------
// out[b,h,w,s,co] = ELU( conv3x3_SAME(x, W_s) ),  W_s = mu + n_s*exp(logstd)
// GEMM: C[65536,1024] = A_im2col[65536,576] * W[576,1024]; C row-major == out.
// fp16 m16n8k16 HMMA + LDSM. Warp tile 64x64 (1.0 smem wf per HMMA) with
// 3 CTAs/SM x 128 thr (12 warps) so the tensor pipe stays issued:
// R7 showed the same tile at 8 warps/SM starves (tensor 44%).
// ---------------------------------------------------------------------------
#define NS    8
#define CINV  64
#define COUTV 128
#define NTOTV 1024
#define NTAP  9
#define PSTR  72
#define BSTR  72
#define PATCH_HALFS (264 * PSTR)            // 4 h-rows x 66 w  (38016 B)
#define BSTAGE_HALFS (128 * BSTR)           // 18432 B
#define NSTAGE 2
#define SMEM_TOTAL ((PATCH_HALFS + NSTAGE * BSTAGE_HALFS) * 2)   // 74880 B -> 3 CTA/SM

__device__ __half g_Xh[16 * 64 * 64 * CINV];
__device__ __half g_Wh[NTAP * NTOTV * CINV];

// ============================ helpers ======================================
__device__ __forceinline__ void cp_async16(uint32_t dst, const void* src) {
    asm volatile("cp.async.cg.shared.global [%0], [%1], 16;" :: "r"(dst), "l"(src));
}
__device__ __forceinline__ void cp_commit() { asm volatile("cp.async.commit_group;"); }
template <int N> __device__ __forceinline__ void cp_wait() {
    asm volatile("cp.async.wait_group %0;" :: "n"(N));
}
__device__ __forceinline__ uint32_t smem_u32(const void* p) {
    uint32_t a;
    asm("{ .reg .u64 t; cvta.to.shared.u64 t, %1; cvt.u32.u64 %0, t; }" : "=r"(a) : "l"(p));
    return a;
}
__device__ __forceinline__ void ldsm4(uint32_t& r0, uint32_t& r1, uint32_t& r2,
                                      uint32_t& r3, uint32_t addr) {
    asm volatile("ldmatrix.sync.aligned.m8n8.x4.shared.b16 {%0,%1,%2,%3}, [%4];"
                 : "=r"(r0), "=r"(r1), "=r"(r2), "=r"(r3) : "r"(addr));
}
__device__ __forceinline__ void mma_f16(float* c, const uint32_t* a, const uint32_t* b) {
    asm volatile(
        "mma.sync.aligned.m16n8k16.row.col.f32.f16.f16.f32 "
        "{%0,%1,%2,%3}, {%4,%5,%6,%7}, {%8,%9}, {%0,%1,%2,%3};"
        : "+f"(c[0]), "+f"(c[1]), "+f"(c[2]), "+f"(c[3])
        : "r"(a[0]), "r"(a[1]), "r"(a[2]), "r"(a[3]), "r"(b[0]), "r"(b[1]));
}
__device__ __forceinline__ float elu1(float v) { return v > 0.f ? v : expm1f(v); }

// ============================ fused prep kernel ============================
__global__ void prep(const float* __restrict__ x,
                     const float* __restrict__ mu,
                     const float* __restrict__ logstd,
                     const float* __restrict__ noise) {
    int idx = blockIdx.x * blockDim.x + threadIdx.x;      // 1048576 threads
    float4 v = reinterpret_cast<const float4*>(x)[idx];
    __half2* xo = reinterpret_cast<__half2*>(g_Xh) + idx * 2;
    xo[0] = __floats2half2_rn(v.x, v.y);
    xo[1] = __floats2half2_rn(v.z, v.w);
    if (idx < NS * NTAP * CINV * COUTV) {                 // 589824
        int co  = idx & 127;
        int ci  = (idx >> 7) & 63;
        int tap = (idx >> 13) % NTAP;
        int s   = idx / (NTAP << 13);
        int mi  = (tap * CINV + ci) * COUTV + co;
        float w = mu[mi] + noise[idx] * expf(logstd[mi]);
        g_Wh[(tap * NTOTV + s * COUTV + co) * CINV + ci] = __float2half_rn(w);
    }
}

// ============================ conv kernel ==================================
__device__ __forceinline__ void load_B(uint32_t b_u32, int tap, int ntile, int tid) {
    const __half* wb = g_Wh + (size_t)(tap * NTOTV + (ntile << 7)) * CINV;
    #pragma unroll
    for (int i = 0; i < 8; i++) {            // 1024 chunks / 128 threads
        int lin = tid + (i << 7);
        int n = lin >> 3, c = lin & 7;
        cp_async16(b_u32 + (uint32_t)(n * BSTR + (c << 3)) * 2u, wb + n * CINV + (c << 3));
    }
    cp_commit();
}

__global__ __launch_bounds__(128, 3)
void conv_mma_kernel(float* __restrict__ out) {
    extern __shared__ __half smem[];
    const uint32_t patch_u32 = smem_u32(smem);
    const uint32_t bu0 = patch_u32 + PATCH_HALFS * 2u;

    const int tid = threadIdx.x, wid = tid >> 5, lid = tid & 31;
    const int mtile = blockIdx.x, ntile = blockIdx.y;
    const int b  = mtile >> 5;
    const int h0 = (mtile & 31) << 1;
    const int wm = wid & 1, wn = wid >> 1;     // 2x2 warps, tile 64m x 64n

    const uint32_t a_lane = (uint32_t)((lid & 15) * PSTR + (lid >> 4) * 8) * 2u;
    const uint32_t b_lane = (uint32_t)((((lid & 7) + ((lid >> 4) << 3)) * BSTR)
                                       + (((lid >> 3) & 1) << 3)) * 2u;
    const uint32_t pA0    = patch_u32 + (uint32_t)(((wm + 1) * 66 + 1) * PSTR * 2) + a_lane;
    const uint32_t b_warp = (uint32_t)((wn << 6) * BSTR) * 2u + b_lane;

    // ---- prologue: G0 = patch + B0, G1 = B1 ----
    #pragma unroll
    for (int i = 0; i < 17; i++) {             // 2112 chunks / 128 threads
        int lin = tid + (i << 7);
        if (lin >= 2112) break;
        int row = lin >> 3, c = lin & 7;
        int hh = row / 66, ww = row % 66;
        int h = h0 - 1 + hh, w = ww - 1;
        uint32_t dst = patch_u32 + (uint32_t)(row * PSTR + (c << 3)) * 2u;
        if ((unsigned)h < 64u && (unsigned)w < 64u) {
            cp_async16(dst, g_Xh + (size_t)(((b << 6) + h) * 64 + w) * CINV + (c << 3));
        } else {
            asm volatile("st.shared.v4.b32 [%0], {%1,%1,%1,%1};" :: "r"(dst), "r"(0u) : "memory");
        }
    }
    load_B(bu0, 0, ntile, tid);                      // closes G0
    load_B(bu0 + BSTAGE_HALFS * 2u, 1, ntile, tid);  // G1

    float acc[4][8][4];
    #pragma unroll
    for (int i = 0; i < 4; i++)
        #pragma unroll
        for (int j = 0; j < 8; j++)
            #pragma unroll
            for (int k = 0; k < 4; k++) acc[i][j][k] = 0.f;

    #pragma unroll 1
    for (int tap = 0; tap < NTAP; tap++) {
        // wait load(tap), make visible, then (safely) overwrite the buffer
        // last read at tap-1 with load(tap+1).
        if (tap == 0) cp_wait<1>(); else cp_wait<0>();
        __syncthreads();
        if (tap >= 1 && tap < 8)
            load_B(bu0 + (uint32_t)(((tap + 1) & 1) * (BSTAGE_HALFS * 2)), tap + 1, ntile, tid);

        const int dy = tap / 3 - 1, dx = tap % 3 - 1;
        const uint32_t aBase0 = pA0 + (uint32_t)((dy * 66 + dx) * PSTR * 2);
        const uint32_t bBase0 = bu0 + (uint32_t)((tap & 1) * (BSTAGE_HALFS * 2)) + b_warp;

        #pragma unroll
        for (int kk = 0; kk < 4; kk++) {
            uint32_t a[4][4], bb[8][2];
            const uint32_t aBase = aBase0 + (uint32_t)(kk * 32);
            const uint32_t bBase = bBase0 + (uint32_t)(kk * 32);
            #pragma unroll
            for (int mf = 0; mf < 4; mf++)
                ldsm4(a[mf][0], a[mf][1], a[mf][2], a[mf][3],
                      aBase + (uint32_t)(mf * 16 * PSTR * 2));
            #pragma unroll
            for (int np = 0; np < 4; np++)
                ldsm4(bb[2 * np][0], bb[2 * np][1], bb[2 * np + 1][0], bb[2 * np + 1][1],
                      bBase + (uint32_t)(np * 16 * BSTR * 2));
            #pragma unroll
            for (int mf = 0; mf < 4; mf++)
                #pragma unroll
                for (int nf = 0; nf < 8; nf++)
                    mma_f16(acc[mf][nf], a[mf], bb[nf]);
        }
    }

    // ---- epilogue: ELU + float2 stores ----
    const int l4 = lid >> 2, lm = lid & 3;
    const int colb = (ntile << 7) + (wn << 6) + lm * 2;
    #pragma unroll
    for (int mf = 0; mf < 4; mf++) {
        int row = (mtile << 7) + wm * 64 + mf * 16 + l4;
        float* o0 = out + (size_t)row * NTOTV + colb;
        float* o1 = o0 + 8 * NTOTV;
        #pragma unroll
        for (int nf = 0; nf < 8; nf++) {
            float2 v0, v1;
            v0.x = elu1(acc[mf][nf][0]); v0.y = elu1(acc[mf][nf][1]);
            v1.x = elu1(acc[mf][nf][2]); v1.y = elu1(acc[mf][nf][3]);
            *reinterpret_cast<float2*>(o0 + nf * 8) = v0;
            *reinterpret_cast<float2*>(o1 + nf * 8) = v1;
        }
    }
}

// ---------------------------------------------------------------------------
extern "C" void kernel_launch(void* const* d_in, const int* in_sizes, int n_in,
                              void* d_out, int out_size) {
    const float* x      = (const float*)d_in[0];
    const float* mu     = (const float*)d_in[1];
    const float* logstd = (const float*)d_in[2];
    const float* noise  = (const float*)d_in[3];
    float* out = (float*)d_out;

    prep<<<4096, 256>>>(x, mu, logstd, noise);

    cudaFuncSetAttribute(conv_mma_kernel,
                         cudaFuncAttributeMaxDynamicSharedMemorySize, SMEM_TOTAL);
    dim3 grid(512, 8);
    conv_mma_kernel<<<grid, 128, SMEM_TOTAL>>>(out);
}

// round 10
// speedup vs baseline: 1.1577x; 1.0763x over previous
#include <cuda_runtime.h>
#include <cuda_fp16.h>
#include <cstdint>

// ---------------------------------------------------------------------------
// out[b,h,w,s,co] = ELU( conv3x3_SAME(x, W_s) ),  W_s = mu + n_s*exp(logstd)
// GEMM: C[65536,1024] = A_im2col[65536,576] * W[576,1024]; C row-major == out.
// fp16 m16n8k16 HMMA + LDSM, 64x32 warp tiles, 16 warps/SM (R6 config), plus
// per-warp kk PHASE STAGGER: warps sharing an SMSP start the (order-free)
// kk loop 2 apart, so one warp's LDSM burst overlaps its partner's HMMA burst
// (R6-R8 showed smem and tensor phases were additive, not overlapped).
// ---------------------------------------------------------------------------
#define NS    8
#define CINV  64
#define COUTV 128
#define NTOTV 1024
#define NTAP  9
#define PSTR  72
#define BSTR  72
#define PATCH_HALFS (264 * PSTR)            // 4 h-rows x 66 w
#define BSTAGE_HALFS (128 * BSTR)
#define NSTAGE 4
#define SMEM_TOTAL ((PATCH_HALFS + NSTAGE * BSTAGE_HALFS) * 2)   // 111744 B -> 2 CTA/SM

__device__ __half g_Xh[16 * 64 * 64 * CINV];
__device__ __half g_Wh[NTAP * NTOTV * CINV];

// ============================ helpers ======================================
__device__ __forceinline__ void cp_async16(uint32_t dst, const void* src) {
    asm volatile("cp.async.cg.shared.global [%0], [%1], 16;" :: "r"(dst), "l"(src));
}
__device__ __forceinline__ void cp_commit() { asm volatile("cp.async.commit_group;"); }
template <int N> __device__ __forceinline__ void cp_wait() {
    asm volatile("cp.async.wait_group %0;" :: "n"(N));
}
__device__ __forceinline__ uint32_t smem_u32(const void* p) {
    uint32_t a;
    asm("{ .reg .u64 t; cvta.to.shared.u64 t, %1; cvt.u32.u64 %0, t; }" : "=r"(a) : "l"(p));
    return a;
}
__device__ __forceinline__ void ldsm4(uint32_t& r0, uint32_t& r1, uint32_t& r2,
                                      uint32_t& r3, uint32_t addr) {
    asm volatile("ldmatrix.sync.aligned.m8n8.x4.shared.b16 {%0,%1,%2,%3}, [%4];"
                 : "=r"(r0), "=r"(r1), "=r"(r2), "=r"(r3) : "r"(addr));
}
__device__ __forceinline__ void mma_f16(float* c, const uint32_t* a, const uint32_t* b) {
    asm volatile(
        "mma.sync.aligned.m16n8k16.row.col.f32.f16.f16.f32 "
        "{%0,%1,%2,%3}, {%4,%5,%6,%7}, {%8,%9}, {%0,%1,%2,%3};"
        : "+f"(c[0]), "+f"(c[1]), "+f"(c[2]), "+f"(c[3])
        : "r"(a[0]), "r"(a[1]), "r"(a[2]), "r"(a[3]), "r"(b[0]), "r"(b[1]));
}
__device__ __forceinline__ float elu1(float v) { return v > 0.f ? v : expm1f(v); }

// ============================ fused prep kernel ============================
__global__ void prep(const float* __restrict__ x,
                     const float* __restrict__ mu,
                     const float* __restrict__ logstd,
                     const float* __restrict__ noise) {
    int idx = blockIdx.x * blockDim.x + threadIdx.x;      // 1048576 threads
    float4 v = reinterpret_cast<const float4*>(x)[idx];
    __half2* xo = reinterpret_cast<__half2*>(g_Xh) + idx * 2;
    xo[0] = __floats2half2_rn(v.x, v.y);
    xo[1] = __floats2half2_rn(v.z, v.w);
    if (idx < NS * NTAP * CINV * COUTV) {                 // 589824
        int co  = idx & 127;
        int ci  = (idx >> 7) & 63;
        int tap = (idx >> 13) % NTAP;
        int s   = idx / (NTAP << 13);
        int mi  = (tap * CINV + ci) * COUTV + co;
        float w = mu[mi] + noise[idx] * expf(logstd[mi]);
        g_Wh[(tap * NTOTV + s * COUTV + co) * CINV + ci] = __float2half_rn(w);
    }
}

// ============================ conv kernel ==================================
__device__ __forceinline__ void load_B(uint32_t b_u32, int tap, int ntile, int tid) {
    const __half* wb = g_Wh + (size_t)(tap * NTOTV + (ntile << 7)) * CINV;
    #pragma unroll
    for (int i = 0; i < 4; i++) {
        int lin = tid + (i << 8);
        int n = lin >> 3, c = lin & 7;
        cp_async16(b_u32 + (uint32_t)(n * BSTR + (c << 3)) * 2u, wb + n * CINV + (c << 3));
    }
    cp_commit();
}

__global__ __launch_bounds__(256, 2)
void conv_mma_kernel(float* __restrict__ out) {
    extern __shared__ __half smem[];
    const uint32_t patch_u32 = smem_u32(smem);
    const uint32_t bu0 = patch_u32 + PATCH_HALFS * 2u;

    const int tid = threadIdx.x, wid = tid >> 5, lid = tid & 31;
    const int mtile = blockIdx.x, ntile = blockIdx.y;
    const int b  = mtile >> 5;
    const int h0 = (mtile & 31) << 1;
    const int wm = wid & 1, wn = wid >> 1;     // warp tile 64m x 32n
    const int koff = (wid & 3) ^ ((wid >> 2) << 1);   // SMSP partners differ by 2

    const uint32_t a_lane = (uint32_t)((lid & 15) * PSTR + (lid >> 4) * 8) * 2u;
    const uint32_t b_lane = (uint32_t)((((lid & 7) + ((lid >> 4) << 3)) * BSTR)
                                       + (((lid >> 3) & 1) << 3)) * 2u;
    const uint32_t pA0    = patch_u32 + (uint32_t)(((wm + 1) * 66 + 1) * PSTR * 2) + a_lane;
    const uint32_t b_warp = (uint32_t)((wn << 5) * BSTR) * 2u + b_lane;

    // ---- prologue: G0 = patch + B0, G1 = B1, G2 = B2 ----
    #pragma unroll
    for (int i = 0; i < 9; i++) {              // 2112 chunks / 256 threads
        int lin = tid + (i << 8);
        if (lin >= 2112) break;
        int row = lin >> 3, c = lin & 7;
        int hh = row / 66, ww = row % 66;
        int h = h0 - 1 + hh, w = ww - 1;
        uint32_t dst = patch_u32 + (uint32_t)(row * PSTR + (c << 3)) * 2u;
        if ((unsigned)h < 64u && (unsigned)w < 64u) {
            cp_async16(dst, g_Xh + (size_t)(((b << 6) + h) * 64 + w) * CINV + (c << 3));
        } else {
            asm volatile("st.shared.v4.b32 [%0], {%1,%1,%1,%1};" :: "r"(dst), "r"(0u) : "memory");
        }
    }
    load_B(bu0, 0, ntile, tid);
    load_B(bu0 + BSTAGE_HALFS * 2u, 1, ntile, tid);
    load_B(bu0 + 2u * BSTAGE_HALFS * 2u, 2, ntile, tid);

    float acc[4][4][4];
    #pragma unroll
    for (int i = 0; i < 4; i++)
        #pragma unroll
        for (int j = 0; j < 4; j++)
            #pragma unroll
            for (int k = 0; k < 4; k++) acc[i][j][k] = 0.f;

    cp_wait<1>();              // G0,G1 done
    __syncthreads();

    #pragma unroll 1
    for (int tap = 0; tap < NTAP; tap++) {
        if (tap >= 1) {
            if (tap < 6) cp_wait<1>(); else cp_wait<0>();
            __syncthreads();
        }
        if (tap + 3 <= 8)
            load_B(bu0 + (uint32_t)(((tap + 3) & 3) * (BSTAGE_HALFS * 2)), tap + 3, ntile, tid);

        const int dy = tap / 3 - 1, dx = tap % 3 - 1;
        const uint32_t aBase0 = pA0 + (uint32_t)((dy * 66 + dx) * PSTR * 2);
        const uint32_t bBase0 = bu0 + (uint32_t)((tap & 3) * (BSTAGE_HALFS * 2)) + b_warp;

        #pragma unroll
        for (int kk2 = 0; kk2 < 4; kk2++) {
            const int kk = (kk2 + koff) & 3;   // per-warp phase: order-free accumulation
            uint32_t a[4][4], bb[4][2];
            const uint32_t aBase = aBase0 + (uint32_t)(kk * 32);
            const uint32_t bBase = bBase0 + (uint32_t)(kk * 32);
            #pragma unroll
            for (int mf = 0; mf < 4; mf++)
                ldsm4(a[mf][0], a[mf][1], a[mf][2], a[mf][3],
                      aBase + (uint32_t)(mf * 16 * PSTR * 2));
            #pragma unroll
            for (int np = 0; np < 2; np++)
                ldsm4(bb[2 * np][0], bb[2 * np][1], bb[2 * np + 1][0], bb[2 * np + 1][1],
                      bBase + (uint32_t)(np * 16 * BSTR * 2));
            #pragma unroll
            for (int mf = 0; mf < 4; mf++)
                #pragma unroll
                for (int nf = 0; nf < 4; nf++)
                    mma_f16(acc[mf][nf], a[mf], bb[nf]);
        }
    }

    // ---- epilogue: ELU + float2 stores ----
    const int l4 = lid >> 2, lm = lid & 3;
    const int colb = (ntile << 7) + (wn << 5) + lm * 2;
    #pragma unroll
    for (int mf = 0; mf < 4; mf++) {
        int row = (mtile << 7) + wm * 64 + mf * 16 + l4;
        float* o0 = out + (size_t)row * NTOTV + colb;
        float* o1 = o0 + 8 * NTOTV;
        #pragma unroll
        for (int nf = 0; nf < 4; nf++) {
            float2 v0, v1;
            v0.x = elu1(acc[mf][nf][0]); v0.y = elu1(acc[mf][nf][1]);
            v1.x = elu1(acc[mf][nf][2]); v1.y = elu1(acc[mf][nf][3]);
            *reinterpret_cast<float2*>(o0 + nf * 8) = v0;
            *reinterpret_cast<float2*>(o1 + nf * 8) = v1;
        }
    }
}

// ---------------------------------------------------------------------------
extern "C" void kernel_launch(void* const* d_in, const int* in_sizes, int n_in,
                              void* d_out, int out_size) {
    const float* x      = (const float*)d_in[0];
    const float* mu     = (const float*)d_in[1];
    const float* logstd = (const float*)d_in[2];
    const float* noise  = (const float*)d_in[3];
    float* out = (float*)d_out;

    prep<<<4096, 256>>>(x, mu, logstd, noise);

    cudaFuncSetAttribute(conv_mma_kernel,
                         cudaFuncAttributeMaxDynamicSharedMemorySize, SMEM_TOTAL);
    dim3 grid(512, 8);
    conv_mma_kernel<<<grid, 256, SMEM_TOTAL>>>(out);
}

// round 11
// speedup vs baseline: 1.2565x; 1.0853x over previous
#include <cuda_runtime.h>
#include <cuda_fp16.h>
#include <cstdint>

// ---------------------------------------------------------------------------
// out[b,h,w,s,co] = ELU( conv3x3_SAME(x, W_s) ),  W_s = mu + n_s*exp(logstd)
// GEMM: C[65536,1024] = A_im2col[65536,576] * W[576,1024]; C row-major == out.
// fp16 m16n8k16 HMMA + LDSM, 64x32 warp tiles, 16 warps/SM. Tap loop FULLY
// UNROLLED so dy/dx/stage/kk offsets fold to immediates: R9 showed ~2.8k
// non-essential (mostly ALU addressing) instructions per warp were crowding
// the issue slots and keeping smem/tensor phases additive.
// ---------------------------------------------------------------------------
#define NS    8
#define CINV  64
#define COUTV 128
#define NTOTV 1024
#define NTAP  9
#define PSTR  72
#define BSTR  72
#define PATCH_HALFS (264 * PSTR)            // 4 h-rows x 66 w
#define BSTAGE_HALFS (128 * BSTR)
#define NSTAGE 4
#define SMEM_TOTAL ((PATCH_HALFS + NSTAGE * BSTAGE_HALFS) * 2)   // 111744 B -> 2 CTA/SM

__device__ __half g_Xh[16 * 64 * 64 * CINV];
__device__ __half g_Wh[NTAP * NTOTV * CINV];

// ============================ helpers ======================================
__device__ __forceinline__ void cp_async16(uint32_t dst, const void* src) {
    asm volatile("cp.async.cg.shared.global [%0], [%1], 16;" :: "r"(dst), "l"(src));
}
__device__ __forceinline__ void cp_commit() { asm volatile("cp.async.commit_group;"); }
template <int N> __device__ __forceinline__ void cp_wait() {
    asm volatile("cp.async.wait_group %0;" :: "n"(N));
}
__device__ __forceinline__ uint32_t smem_u32(const void* p) {
    uint32_t a;
    asm("{ .reg .u64 t; cvta.to.shared.u64 t, %1; cvt.u32.u64 %0, t; }" : "=r"(a) : "l"(p));
    return a;
}
__device__ __forceinline__ void ldsm4(uint32_t& r0, uint32_t& r1, uint32_t& r2,
                                      uint32_t& r3, uint32_t addr) {
    asm volatile("ldmatrix.sync.aligned.m8n8.x4.shared.b16 {%0,%1,%2,%3}, [%4];"
                 : "=r"(r0), "=r"(r1), "=r"(r2), "=r"(r3) : "r"(addr));
}
__device__ __forceinline__ void mma_f16(float* c, const uint32_t* a, const uint32_t* b) {
    asm volatile(
        "mma.sync.aligned.m16n8k16.row.col.f32.f16.f16.f32 "
        "{%0,%1,%2,%3}, {%4,%5,%6,%7}, {%8,%9}, {%0,%1,%2,%3};"
        : "+f"(c[0]), "+f"(c[1]), "+f"(c[2]), "+f"(c[3])
        : "r"(a[0]), "r"(a[1]), "r"(a[2]), "r"(a[3]), "r"(b[0]), "r"(b[1]));
}
__device__ __forceinline__ float elu1(float v) { return v > 0.f ? v : expm1f(v); }

// ============================ fused prep kernel ============================
__global__ void prep(const float* __restrict__ x,
                     const float* __restrict__ mu,
                     const float* __restrict__ logstd,
                     const float* __restrict__ noise) {
    int idx = blockIdx.x * blockDim.x + threadIdx.x;      // 1048576 threads
    float4 v = reinterpret_cast<const float4*>(x)[idx];
    __half2* xo = reinterpret_cast<__half2*>(g_Xh) + idx * 2;
    xo[0] = __floats2half2_rn(v.x, v.y);
    xo[1] = __floats2half2_rn(v.z, v.w);
    if (idx < NS * NTAP * CINV * COUTV) {                 // 589824
        int co  = idx & 127;
        int ci  = (idx >> 7) & 63;
        int tap = (idx >> 13) % NTAP;
        int s   = idx / (NTAP << 13);
        int mi  = (tap * CINV + ci) * COUTV + co;
        float w = mu[mi] + noise[idx] * expf(logstd[mi]);
        g_Wh[(tap * NTOTV + s * COUTV + co) * CINV + ci] = __float2half_rn(w);
    }
}

// ============================ conv kernel ==================================
__device__ __forceinline__ void load_B(uint32_t b_u32, int tap, int ntile, int tid) {
    const __half* wb = g_Wh + (size_t)(tap * NTOTV + (ntile << 7)) * CINV;
    #pragma unroll
    for (int i = 0; i < 4; i++) {
        int lin = tid + (i << 8);
        int n = lin >> 3, c = lin & 7;
        cp_async16(b_u32 + (uint32_t)(n * BSTR + (c << 3)) * 2u, wb + n * CINV + (c << 3));
    }
    cp_commit();
}

__global__ __launch_bounds__(256, 2)
void conv_mma_kernel(float* __restrict__ out) {
    extern __shared__ __half smem[];
    const uint32_t patch_u32 = smem_u32(smem);
    const uint32_t bu0 = patch_u32 + PATCH_HALFS * 2u;

    const int tid = threadIdx.x, wid = tid >> 5, lid = tid & 31;
    const int mtile = blockIdx.x, ntile = blockIdx.y;
    const int b  = mtile >> 5;
    const int h0 = (mtile & 31) << 1;
    const int wm = wid & 1, wn = wid >> 1;     // warp tile 64m x 32n

    const uint32_t a_lane = (uint32_t)((lid & 15) * PSTR + (lid >> 4) * 8) * 2u;
    const uint32_t b_lane = (uint32_t)((((lid & 7) + ((lid >> 4) << 3)) * BSTR)
                                       + (((lid >> 3) & 1) << 3)) * 2u;
    const uint32_t pA0    = patch_u32 + (uint32_t)(((wm + 1) * 66 + 1) * PSTR * 2) + a_lane;
    const uint32_t b_warp = bu0 + (uint32_t)((wn << 5) * BSTR) * 2u + b_lane;

    // ---- prologue: G0 = patch + B0, G1 = B1, G2 = B2 ----
    #pragma unroll
    for (int i = 0; i < 9; i++) {              // 2112 chunks / 256 threads
        int lin = tid + (i << 8);
        if (lin >= 2112) break;
        int row = lin >> 3, c = lin & 7;
        int hh = row / 66, ww = row % 66;
        int h = h0 - 1 + hh, w = ww - 1;
        uint32_t dst = patch_u32 + (uint32_t)(row * PSTR + (c << 3)) * 2u;
        if ((unsigned)h < 64u && (unsigned)w < 64u) {
            cp_async16(dst, g_Xh + (size_t)(((b << 6) + h) * 64 + w) * CINV + (c << 3));
        } else {
            asm volatile("st.shared.v4.b32 [%0], {%1,%1,%1,%1};" :: "r"(dst), "r"(0u) : "memory");
        }
    }
    load_B(bu0, 0, ntile, tid);
    load_B(bu0 + BSTAGE_HALFS * 2u, 1, ntile, tid);
    load_B(bu0 + 2u * BSTAGE_HALFS * 2u, 2, ntile, tid);

    float acc[4][4][4];
    #pragma unroll
    for (int i = 0; i < 4; i++)
        #pragma unroll
        for (int j = 0; j < 4; j++)
            #pragma unroll
            for (int k = 0; k < 4; k++) acc[i][j][k] = 0.f;

    cp_wait<1>();              // G0,G1 done
    __syncthreads();

    #pragma unroll              // FULL unroll: tap compile-time -> imm offsets
    for (int tap = 0; tap < NTAP; tap++) {
        if (tap >= 1) {
            if (tap < 6) cp_wait<1>(); else cp_wait<0>();
            __syncthreads();
        }
        if (tap + 3 <= 8)
            load_B(bu0 + (uint32_t)(((tap + 3) & 3) * (BSTAGE_HALFS * 2)), tap + 3, ntile, tid);

        const int dy = tap / 3 - 1, dx = tap % 3 - 1;          // constexpr-folded
        const uint32_t aBase0 = pA0 + (uint32_t)((dy * 66 + dx) * PSTR * 2);
        const uint32_t bBase0 = b_warp + (uint32_t)((tap & 3) * (BSTAGE_HALFS * 2));

        #pragma unroll
        for (int kk = 0; kk < 4; kk++) {
            uint32_t a[4][4], bb[4][2];
            const uint32_t aBase = aBase0 + (uint32_t)(kk * 32);
            const uint32_t bBase = bBase0 + (uint32_t)(kk * 32);
            #pragma unroll
            for (int mf = 0; mf < 4; mf++)
                ldsm4(a[mf][0], a[mf][1], a[mf][2], a[mf][3],
                      aBase + (uint32_t)(mf * 16 * PSTR * 2));
            #pragma unroll
            for (int np = 0; np < 2; np++)
                ldsm4(bb[2 * np][0], bb[2 * np][1], bb[2 * np + 1][0], bb[2 * np + 1][1],
                      bBase + (uint32_t)(np * 16 * BSTR * 2));
            #pragma unroll
            for (int mf = 0; mf < 4; mf++)
                #pragma unroll
                for (int nf = 0; nf < 4; nf++)
                    mma_f16(acc[mf][nf], a[mf], bb[nf]);
        }
    }

    // ---- epilogue: ELU + float2 stores ----
    const int l4 = lid >> 2, lm = lid & 3;
    const int colb = (ntile << 7) + (wn << 5) + lm * 2;
    #pragma unroll
    for (int mf = 0; mf < 4; mf++) {
        int row = (mtile << 7) + wm * 64 + mf * 16 + l4;
        float* o0 = out + (size_t)row * NTOTV + colb;
        float* o1 = o0 + 8 * NTOTV;
        #pragma unroll
        for (int nf = 0; nf < 4; nf++) {
            float2 v0, v1;
            v0.x = elu1(acc[mf][nf][0]); v0.y = elu1(acc[mf][nf][1]);
            v1.x = elu1(acc[mf][nf][2]); v1.y = elu1(acc[mf][nf][3]);
            *reinterpret_cast<float2*>(o0 + nf * 8) = v0;
            *reinterpret_cast<float2*>(o1 + nf * 8) = v1;
        }
    }
}

// ---------------------------------------------------------------------------
extern "C" void kernel_launch(void* const* d_in, const int* in_sizes, int n_in,
                              void* d_out, int out_size) {
    const float* x      = (const float*)d_in[0];
    const float* mu     = (const float*)d_in[1];
    const float* logstd = (const float*)d_in[2];
    const float* noise  = (const float*)d_in[3];
    float* out = (float*)d_out;

    prep<<<4096, 256>>>(x, mu, logstd, noise);

    cudaFuncSetAttribute(conv_mma_kernel,
                         cudaFuncAttributeMaxDynamicSharedMemorySize, SMEM_TOTAL);
    dim3 grid(512, 8);
    conv_mma_kernel<<<grid, 256, SMEM_TOTAL>>>(out);
}

// round 12
// speedup vs baseline: 1.3624x; 1.0843x over previous
#include <cuda_runtime.h>
#include <cuda_fp16.h>
#include <cstdint>

// ---------------------------------------------------------------------------
// out[b,h,w,s,co] = ELU( conv3x3_SAME(x, W_s) ),  W_s = mu + n_s*exp(logstd)
// GEMM: C[65536,1024] = A_im2col[65536,576] * W[576,1024]; C row-major == out.
// fp16 m16n8k16 HMMA + LDSM, 64x32 warp tiles, 16 warps/SM.
// R10 (fully unrolled taps, imm addressing) + R6 (register frag double-buffer)
// so each warp's LDSM for step k+1 overlaps its own HMMAs for step k.
// ---------------------------------------------------------------------------
#define NS    8
#define CINV  64
#define COUTV 128
#define NTOTV 1024
#define NTAP  9
#define PSTR  72
#define BSTR  72
#define PATCH_HALFS (264 * PSTR)            // 4 h-rows x 66 w
#define BSTAGE_HALFS (128 * BSTR)
#define NSTAGE 4
#define SMEM_TOTAL ((PATCH_HALFS + NSTAGE * BSTAGE_HALFS) * 2)   // 111744 B -> 2 CTA/SM

__device__ __half g_Xh[16 * 64 * 64 * CINV];
__device__ __half g_Wh[NTAP * NTOTV * CINV];

// ============================ helpers ======================================
__device__ __forceinline__ void cp_async16(uint32_t dst, const void* src) {
    asm volatile("cp.async.cg.shared.global [%0], [%1], 16;" :: "r"(dst), "l"(src));
}
__device__ __forceinline__ void cp_commit() { asm volatile("cp.async.commit_group;"); }
template <int N> __device__ __forceinline__ void cp_wait() {
    asm volatile("cp.async.wait_group %0;" :: "n"(N));
}
__device__ __forceinline__ uint32_t smem_u32(const void* p) {
    uint32_t a;
    asm("{ .reg .u64 t; cvta.to.shared.u64 t, %1; cvt.u32.u64 %0, t; }" : "=r"(a) : "l"(p));
    return a;
}
__device__ __forceinline__ void ldsm4(uint32_t& r0, uint32_t& r1, uint32_t& r2,
                                      uint32_t& r3, uint32_t addr) {
    asm volatile("ldmatrix.sync.aligned.m8n8.x4.shared.b16 {%0,%1,%2,%3}, [%4];"
                 : "=r"(r0), "=r"(r1), "=r"(r2), "=r"(r3) : "r"(addr));
}
__device__ __forceinline__ void mma_f16(float* c, const uint32_t* a, const uint32_t* b) {
    asm volatile(
        "mma.sync.aligned.m16n8k16.row.col.f32.f16.f16.f32 "
        "{%0,%1,%2,%3}, {%4,%5,%6,%7}, {%8,%9}, {%0,%1,%2,%3};"
        : "+f"(c[0]), "+f"(c[1]), "+f"(c[2]), "+f"(c[3])
        : "r"(a[0]), "r"(a[1]), "r"(a[2]), "r"(a[3]), "r"(b[0]), "r"(b[1]));
}
__device__ __forceinline__ float elu1(float v) {      // fast ELU (|err| << 1e-3)
    return v > 0.f ? v : (__expf(v) - 1.0f);
}

struct Frags { uint32_t a[4][4]; uint32_t b[4][2]; };

// ============================ fused prep kernel ============================
__global__ void prep(const float* __restrict__ x,
                     const float* __restrict__ mu,
                     const float* __restrict__ logstd,
                     const float* __restrict__ noise) {
    int idx = blockIdx.x * blockDim.x + threadIdx.x;      // 1048576 threads
    float4 v = reinterpret_cast<const float4*>(x)[idx];
    __half2* xo = reinterpret_cast<__half2*>(g_Xh) + idx * 2;
    xo[0] = __floats2half2_rn(v.x, v.y);
    xo[1] = __floats2half2_rn(v.z, v.w);
    if (idx < NS * NTAP * CINV * COUTV) {                 // 589824
        int co  = idx & 127;
        int ci  = (idx >> 7) & 63;
        int tap = (idx >> 13) % NTAP;
        int s   = idx / (NTAP << 13);
        int mi  = (tap * CINV + ci) * COUTV + co;
        float w = mu[mi] + noise[idx] * expf(logstd[mi]);
        g_Wh[(tap * NTOTV + s * COUTV + co) * CINV + ci] = __float2half_rn(w);
    }
}

// ============================ conv kernel ==================================
__device__ __forceinline__ void load_B(uint32_t b_u32, int tap, int ntile, int tid) {
    const __half* wb = g_Wh + (size_t)(tap * NTOTV + (ntile << 7)) * CINV;
    #pragma unroll
    for (int i = 0; i < 4; i++) {
        int lin = tid + (i << 8);
        int n = lin >> 3, c = lin & 7;
        cp_async16(b_u32 + (uint32_t)(n * BSTR + (c << 3)) * 2u, wb + n * CINV + (c << 3));
    }
    cp_commit();
}

// tap/kk are always compile-time constants here -> pure immediate offsets
__device__ __forceinline__ void load_frags(Frags& F, int tap, int kk,
                                           uint32_t pA0, uint32_t b_warp) {
    const int dy = tap / 3 - 1, dx = tap % 3 - 1;
    const uint32_t aBase = pA0 + (uint32_t)((dy * 66 + dx) * PSTR * 2 + kk * 32);
    const uint32_t bBase = b_warp + (uint32_t)((tap & 3) * (BSTAGE_HALFS * 2) + kk * 32);
    #pragma unroll
    for (int mf = 0; mf < 4; mf++)
        ldsm4(F.a[mf][0], F.a[mf][1], F.a[mf][2], F.a[mf][3],
              aBase + (uint32_t)(mf * 16 * PSTR * 2));
    #pragma unroll
    for (int np = 0; np < 2; np++)
        ldsm4(F.b[2 * np][0], F.b[2 * np][1], F.b[2 * np + 1][0], F.b[2 * np + 1][1],
              bBase + (uint32_t)(np * 16 * BSTR * 2));
}

__global__ __launch_bounds__(256, 2)
void conv_mma_kernel(float* __restrict__ out) {
    extern __shared__ __half smem[];
    const uint32_t patch_u32 = smem_u32(smem);
    const uint32_t bu0 = patch_u32 + PATCH_HALFS * 2u;

    const int tid = threadIdx.x, wid = tid >> 5, lid = tid & 31;
    const int mtile = blockIdx.x, ntile = blockIdx.y;
    const int b  = mtile >> 5;
    const int h0 = (mtile & 31) << 1;
    const int wm = wid & 1, wn = wid >> 1;     // warp tile 64m x 32n

    const uint32_t a_lane = (uint32_t)((lid & 15) * PSTR + (lid >> 4) * 8) * 2u;
    const uint32_t b_lane = (uint32_t)((((lid & 7) + ((lid >> 4) << 3)) * BSTR)
                                       + (((lid >> 3) & 1) << 3)) * 2u;
    const uint32_t pA0    = patch_u32 + (uint32_t)(((wm + 1) * 66 + 1) * PSTR * 2) + a_lane;
    const uint32_t b_warp = bu0 + (uint32_t)((wn << 5) * BSTR) * 2u + b_lane;

    // ---- prologue: G0 = patch + B0, G1 = B1, G2 = B2 ----
    #pragma unroll
    for (int i = 0; i < 9; i++) {              // 2112 chunks / 256 threads
        int lin = tid + (i << 8);
        if (lin >= 2112) break;
        int row = lin >> 3, c = lin & 7;
        int hh = row / 66, ww = row % 66;
        int h = h0 - 1 + hh, w = ww - 1;
        uint32_t dst = patch_u32 + (uint32_t)(row * PSTR + (c << 3)) * 2u;
        if ((unsigned)h < 64u && (unsigned)w < 64u) {
            cp_async16(dst, g_Xh + (size_t)(((b << 6) + h) * 64 + w) * CINV + (c << 3));
        } else {
            asm volatile("st.shared.v4.b32 [%0], {%1,%1,%1,%1};" :: "r"(dst), "r"(0u) : "memory");
        }
    }
    load_B(bu0, 0, ntile, tid);
    load_B(bu0 + BSTAGE_HALFS * 2u, 1, ntile, tid);
    load_B(bu0 + 2u * BSTAGE_HALFS * 2u, 2, ntile, tid);

    float acc[4][4][4];
    #pragma unroll
    for (int i = 0; i < 4; i++)
        #pragma unroll
        for (int j = 0; j < 4; j++)
            #pragma unroll
            for (int k = 0; k < 4; k++) acc[i][j][k] = 0.f;

    cp_wait<1>();              // G0,G1 complete
    __syncthreads();

    Frags f[2];
    load_frags(f[0], 0, 0, pA0, b_warp);

    #pragma unroll              // FULL unroll: all offsets immediate
    for (int tap = 0; tap < NTAP; tap++) {
        if (tap >= 1) {
            if (tap < 6) cp_wait<1>(); else cp_wait<0>();
            __syncthreads();
        }
        if (tap + 3 <= 8)
            load_B(bu0 + (uint32_t)(((tap + 3) & 3) * (BSTAGE_HALFS * 2)), tap + 3, ntile, tid);

        #pragma unroll
        for (int kk = 0; kk < 4; kk++) {
            Frags& cur = f[kk & 1];
            Frags& nxt = f[(kk & 1) ^ 1];
            if (kk < 3)        load_frags(nxt, tap, kk + 1, pA0, b_warp);
            else if (tap < 8)  load_frags(nxt, tap + 1, 0, pA0, b_warp);
            #pragma unroll
            for (int mf = 0; mf < 4; mf++)
                #pragma unroll
                for (int nf = 0; nf < 4; nf++)
                    mma_f16(acc[mf][nf], cur.a[mf], cur.b[nf]);
        }
    }

    // ---- epilogue: fast ELU + float2 stores ----
    const int l4 = lid >> 2, lm = lid & 3;
    const int colb = (ntile << 7) + (wn << 5) + lm * 2;
    #pragma unroll
    for (int mf = 0; mf < 4; mf++) {
        int row = (mtile << 7) + wm * 64 + mf * 16 + l4;
        float* o0 = out + (size_t)row * NTOTV + colb;
        float* o1 = o0 + 8 * NTOTV;
        #pragma unroll
        for (int nf = 0; nf < 4; nf++) {
            float2 v0, v1;
            v0.x = elu1(acc[mf][nf][0]); v0.y = elu1(acc[mf][nf][1]);
            v1.x = elu1(acc[mf][nf][2]); v1.y = elu1(acc[mf][nf][3]);
            *reinterpret_cast<float2*>(o0 + nf * 8) = v0;
            *reinterpret_cast<float2*>(o1 + nf * 8) = v1;
        }
    }
}

// ---------------------------------------------------------------------------
extern "C" void kernel_launch(void* const* d_in, const int* in_sizes, int n_in,
                              void* d_out, int out_size) {
    const float* x      = (const float*)d_in[0];
    const float* mu     = (const float*)d_in[1];
    const float* logstd = (const float*)d_in[2];
    const float* noise  = (const float*)d_in[3];
    float* out = (float*)d_out;

    prep<<<4096, 256>>>(x, mu, logstd, noise);

    cudaFuncSetAttribute(conv_mma_kernel,
                         cudaFuncAttributeMaxDynamicSharedMemorySize, SMEM_TOTAL);
    dim3 grid(512, 8);
    conv_mma_kernel<<<grid, 256, SMEM_TOTAL>>>(out);
}

// round 13
// speedup vs baseline: 1.5187x; 1.1147x over previous
#include <cuda_runtime.h>
#include <cuda_fp16.h>
#include <cstdint>

// ---------------------------------------------------------------------------
// out[b,h,w,s,co] = ELU( conv3x3_SAME(x, W_s) ),  W_s = mu + n_s*exp(logstd)
// GEMM: C[65536,1024] = A_im2col[65536,576] * W[576,1024]; C row-major == out.
// fp16 m16n8k16 HMMA. A: CTA-resident smem halo patch + LDSM. B: weights
// pre-packed in MMA FRAGMENT ORDER in gmem -> one coalesced LDG.64 per frag,
// no B smem, no cp.async, ZERO mainloop barriers (warps free-run over taps).
// ---------------------------------------------------------------------------
#define NS    8
#define CINV  64
#define COUTV 128
#define NTOTV 1024
#define NTAP  9
#define PSTR  72
#define PATCH_HALFS (264 * PSTR)            // 4 h-rows x 66 w
#define SMEM_TOTAL (PATCH_HALFS * 2)        // 38016 B

__device__ __half g_Xh[16 * 64 * 64 * CINV];
// B in fragment order: [tap][n8=0..127][kk=0..3][lane=0..31] -> uint2 {b0,b1}
__device__ uint2 g_Wf[NTAP * 128 * 4 * 32];

// ============================ helpers ======================================
__device__ __forceinline__ void cp_async16(uint32_t dst, const void* src) {
    asm volatile("cp.async.cg.shared.global [%0], [%1], 16;" :: "r"(dst), "l"(src));
}
__device__ __forceinline__ void cp_commit() { asm volatile("cp.async.commit_group;"); }
template <int N> __device__ __forceinline__ void cp_wait() {
    asm volatile("cp.async.wait_group %0;" :: "n"(N));
}
__device__ __forceinline__ uint32_t smem_u32(const void* p) {
    uint32_t a;
    asm("{ .reg .u64 t; cvta.to.shared.u64 t, %1; cvt.u32.u64 %0, t; }" : "=r"(a) : "l"(p));
    return a;
}
__device__ __forceinline__ void ldsm4(uint32_t& r0, uint32_t& r1, uint32_t& r2,
                                      uint32_t& r3, uint32_t addr) {
    asm volatile("ldmatrix.sync.aligned.m8n8.x4.shared.b16 {%0,%1,%2,%3}, [%4];"
                 : "=r"(r0), "=r"(r1), "=r"(r2), "=r"(r3) : "r"(addr));
}
__device__ __forceinline__ void mma_f16(float* c, const uint32_t* a, uint2 b) {
    asm volatile(
        "mma.sync.aligned.m16n8k16.row.col.f32.f16.f16.f32 "
        "{%0,%1,%2,%3}, {%4,%5,%6,%7}, {%8,%9}, {%0,%1,%2,%3};"
        : "+f"(c[0]), "+f"(c[1]), "+f"(c[2]), "+f"(c[3])
        : "r"(a[0]), "r"(a[1]), "r"(a[2]), "r"(a[3]), "r"(b.x), "r"(b.y));
}
__device__ __forceinline__ float elu1(float v) {
    return v > 0.f ? v : (__expf(v) - 1.0f);
}

struct Frags { uint32_t a[4][4]; uint2 b[4]; };

// ============================ fused prep kernel ============================
__global__ void prep(const float* __restrict__ x,
                     const float* __restrict__ mu,
                     const float* __restrict__ logstd,
                     const float* __restrict__ noise) {
    int idx = blockIdx.x * blockDim.x + threadIdx.x;      // 1048576 threads
    float4 v = reinterpret_cast<const float4*>(x)[idx];
    __half2* xo = reinterpret_cast<__half2*>(g_Xh) + idx * 2;
    xo[0] = __floats2half2_rn(v.x, v.y);
    xo[1] = __floats2half2_rn(v.z, v.w);

    // Weight fragments: one thread per (tap,n8,kk,lane) = 147456 threads,
    // each computes the 4 halfs of its lane's {b0,b1}.
    if (idx < NTAP * 128 * 4 * 32) {
        int lane = idx & 31;
        int kk   = (idx >> 5) & 3;
        int n8   = (idx >> 7) & 127;
        int tap  = idx >> 14;
        int n  = (n8 << 3) + (lane >> 2);       // global n = s*128+co
        int s  = n >> 7, co = n & 127;
        int k0 = (kk << 4) + ((lane & 3) << 1); // ci of b0 low half
        float w[4];
        #pragma unroll
        for (int j = 0; j < 4; j++) {
            int ci = k0 + (j >> 1) * 8 + (j & 1);
            int mi = (tap * CINV + ci) * COUTV + co;
            int ni = ((s * NTAP + tap) * CINV + ci) * COUTV + co;
            w[j] = mu[mi] + noise[ni] * expf(logstd[mi]);
        }
        uint2 r;
        __half2 h0 = __floats2half2_rn(w[0], w[1]);
        __half2 h1 = __floats2half2_rn(w[2], w[3]);
        r.x = *reinterpret_cast<uint32_t*>(&h0);
        r.y = *reinterpret_cast<uint32_t*>(&h1);
        g_Wf[idx] = r;
    }
}

// ============================ conv kernel ==================================
// tap/kk compile-time -> all offsets immediate.
__device__ __forceinline__ void load_frags(Frags& F, int tap, int kk,
                                           uint32_t pA0, const uint2* wf) {
    const int dy = tap / 3 - 1, dx = tap % 3 - 1;
    const uint32_t aBase = pA0 + (uint32_t)((dy * 66 + dx) * PSTR * 2 + kk * 32);
    #pragma unroll
    for (int mf = 0; mf < 4; mf++)
        ldsm4(F.a[mf][0], F.a[mf][1], F.a[mf][2], F.a[mf][3],
              aBase + (uint32_t)(mf * 16 * PSTR * 2));
    #pragma unroll
    for (int nf = 0; nf < 4; nf++)
        F.b[nf] = __ldg(wf + tap * (128 * 4 * 32 / 32) * 32 + nf * 128 + kk * 32);
}

__global__ __launch_bounds__(256, 2)
void conv_mma_kernel(float* __restrict__ out) {
    extern __shared__ __half smem[];
    const uint32_t patch_u32 = smem_u32(smem);

    const int tid = threadIdx.x, wid = tid >> 5, lid = tid & 31;
    const int mtile = blockIdx.x, ntile = blockIdx.y;
    const int b  = mtile >> 5;
    const int h0 = (mtile & 31) << 1;
    const int wm = wid & 1, wn = wid >> 1;     // warp tile 64m x 32n

    const uint32_t a_lane = (uint32_t)((lid & 15) * PSTR + (lid >> 4) * 8) * 2u;
    const uint32_t pA0    = patch_u32 + (uint32_t)(((wm + 1) * 66 + 1) * PSTR * 2) + a_lane;
    // per-warp fragment pointer: covers nf/kk/tap via immediates
    const uint2* wf = g_Wf + ((size_t)(ntile * 16 + wn * 4) << 7) + lid;

    // ---- prologue: load halo patch once ----
    #pragma unroll
    for (int i = 0; i < 9; i++) {              // 2112 chunks / 256 threads
        int lin = tid + (i << 8);
        if (lin >= 2112) break;
        int row = lin >> 3, c = lin & 7;
        int hh = row / 66, ww = row % 66;
        int h = h0 - 1 + hh, w = ww - 1;
        uint32_t dst = patch_u32 + (uint32_t)(row * PSTR + (c << 3)) * 2u;
        if ((unsigned)h < 64u && (unsigned)w < 64u) {
            cp_async16(dst, g_Xh + (size_t)(((b << 6) + h) * 64 + w) * CINV + (c << 3));
        } else {
            asm volatile("st.shared.v4.b32 [%0], {%1,%1,%1,%1};" :: "r"(dst), "r"(0u) : "memory");
        }
    }
    cp_commit();

    float acc[4][4][4];
    #pragma unroll
    for (int i = 0; i < 4; i++)
        #pragma unroll
        for (int j = 0; j < 4; j++)
            #pragma unroll
            for (int k = 0; k < 4; k++) acc[i][j][k] = 0.f;

    cp_wait<0>();
    __syncthreads();           // the ONLY barrier: patch visible to all warps

    Frags f[2];
    load_frags(f[0], 0, 0, pA0, wf);

    #pragma unroll              // full unroll: tap/kk immediate everywhere
    for (int tap = 0; tap < NTAP; tap++) {
        #pragma unroll
        for (int kk = 0; kk < 4; kk++) {
            Frags& cur = f[kk & 1];
            Frags& nxt = f[(kk & 1) ^ 1];
            if (kk < 3)        load_frags(nxt, tap, kk + 1, pA0, wf);
            else if (tap < 8)  load_frags(nxt, tap + 1, 0, pA0, wf);
            #pragma unroll
            for (int mf = 0; mf < 4; mf++)
                #pragma unroll
                for (int nf = 0; nf < 4; nf++)
                    mma_f16(acc[mf][nf], cur.a[mf], cur.b[nf]);
        }
    }

    // ---- epilogue: fast ELU + float2 stores ----
    const int l4 = lid >> 2, lm = lid & 3;
    const int colb = (ntile << 7) + (wn << 5) + lm * 2;
    #pragma unroll
    for (int mf = 0; mf < 4; mf++) {
        int row = (mtile << 7) + wm * 64 + mf * 16 + l4;
        float* o0 = out + (size_t)row * NTOTV + colb;
        float* o1 = o0 + 8 * NTOTV;
        #pragma unroll
        for (int nf = 0; nf < 4; nf++) {
            float2 v0, v1;
            v0.x = elu1(acc[mf][nf][0]); v0.y = elu1(acc[mf][nf][1]);
            v1.x = elu1(acc[mf][nf][2]); v1.y = elu1(acc[mf][nf][3]);
            *reinterpret_cast<float2*>(o0 + nf * 8) = v0;
            *reinterpret_cast<float2*>(o1 + nf * 8) = v1;
        }
    }
}

// ---------------------------------------------------------------------------
extern "C" void kernel_launch(void* const* d_in, const int* in_sizes, int n_in,
                              void* d_out, int out_size) {
    const float* x      = (const float*)d_in[0];
    const float* mu     = (const float*)d_in[1];
    const float* logstd = (const float*)d_in[2];
    const float* noise  = (const float*)d_in[3];
    float* out = (float*)d_out;

    prep<<<4096, 256>>>(x, mu, logstd, noise);

    dim3 grid(512, 8);
    conv_mma_kernel<<<grid, 256, SMEM_TOTAL>>>(out);
}